// round 7
// baseline (speedup 1.0000x reference)
#include <cuda_runtime.h>
#include <math.h>

#define BB 512
#define SS 1024
#define TT 52
#define START_TAG 50
#define END_TAG 51
#define LOG2E 1.4426950408889634f
#define LN2 0.6931471805599453

typedef unsigned long long ull;

// ---------------- device scratch (no allocations allowed) ----------------
__device__ __align__(16) float g_E[TT * TT];   // exp(transitions)
__device__ int    g_len[BB];
__device__ int    g_isU8;
__device__ __align__(8) float g_alpha[BB][64];
__device__ __align__(8) float g_beta[BB][64];
__device__ int    g_Ka[BB], g_Kb[BB];
__device__ float  g_m0[BB];
__device__ double g_gold[BB];

// ---------------- packed f32x2 helpers (Blackwell) ----------------
__device__ __forceinline__ ull f2pack(float lo, float hi) {
    ull r;
    asm("mov.b64 %0, {%1, %2};" : "=l"(r) : "f"(lo), "f"(hi));
    return r;
}
__device__ __forceinline__ float2 f2unpack(ull a) {
    float2 r;
    asm("mov.b64 {%0, %1}, %2;" : "=f"(r.x), "=f"(r.y) : "l"(a));
    return r;
}
__device__ __forceinline__ float f2lo(ull a) {
    float r;
    asm("{ .reg .b32 hi; mov.b64 {%0, hi}, %1; }" : "=f"(r) : "l"(a));
    return r;
}
__device__ __forceinline__ ull f2fma(ull a, ull b, ull c) {
    ull d;
    asm("fma.rn.f32x2 %0, %1, %2, %3;" : "=l"(d) : "l"(a), "l"(b), "l"(c));
    return d;
}
__device__ __forceinline__ ull f2mul(ull a, ull b) {
    ull d;
    asm("mul.rn.f32x2 %0, %1, %2;" : "=l"(d) : "l"(a), "l"(b));
    return d;
}
__device__ __forceinline__ ull f2add(ull a, ull b) {
    ull d;
    asm("add.rn.f32x2 %0, %1, %2;" : "=l"(d) : "l"(a), "l"(b));
    return d;
}
__device__ __forceinline__ float ex2(float x) {
    float y;
    asm("ex2.approx.ftz.f32 %0, %1;" : "=f"(y) : "f"(x));
    return y;
}

// matvec: u = sum over 26 packed i-pairs of q (in qv) times Ep, 4 accums
__device__ __forceinline__ float matvec26(const ulonglong2* qv, const ull* Ep) {
    ull a0 = f2mul(qv[0].x, Ep[0]);
    ull a1 = f2mul(qv[0].y, Ep[1]);
    ull a2 = f2mul(qv[1].x, Ep[2]);
    ull a3 = f2mul(qv[1].y, Ep[3]);
    #pragma unroll
    for (int c = 2; c < 13; c++) {
        if (c & 1) {
            a2 = f2fma(qv[c].x, Ep[2 * c],     a2);
            a3 = f2fma(qv[c].y, Ep[2 * c + 1], a3);
        } else {
            a0 = f2fma(qv[c].x, Ep[2 * c],     a0);
            a1 = f2fma(qv[c].y, Ep[2 * c + 1], a1);
        }
    }
    a0 = f2add(a0, a2);
    a1 = f2add(a1, a3);
    a0 = f2add(a0, a1);
    float2 h = f2unpack(a0);
    return h.x + h.y;
}

// ---------------- mask dtype detection + E table ----------------
__global__ void k_detect(const void* mask, const float* __restrict__ tr) {
    int tid = threadIdx.x;     // 256
    if (tid < 32) {
        const unsigned char* p = (const unsigned char*)mask;
        int any = 0;
        for (int b = tid; b < BB; b += 32)
            any |= (int)p[(size_t)b * SS + 1];
        #pragma unroll
        for (int o = 16; o; o >>= 1) any |= __shfl_xor_sync(0xffffffffu, any, o);
        if (tid == 0) g_isU8 = (any != 0);
    }
    for (int idx = tid; idx < TT * TT; idx += 256)
        g_E[idx] = expf(tr[idx]);
}

// ---------------- fused length + gold score: one 256-thr CTA per row -----
__global__ void k_lengold(const void* mask,
                          const float* __restrict__ feats,
                          const int* __restrict__ tags,
                          const float* __restrict__ tr) {
    int b    = blockIdx.x;
    int tid  = threadIdx.x;      // 256
    int w    = tid >> 5;
    int lane = tid & 31;
    __shared__ int    slen[8];
    __shared__ double sgold[8];
    __shared__ int    len_sh;

    int cnt = 0;
    if (g_isU8) {
        const unsigned char* p = (const unsigned char*)mask + (size_t)b * SS;
        for (int s = tid; s < SS; s += 256) cnt += (p[s] != 0);
    } else {
        const unsigned int* p = (const unsigned int*)mask + (size_t)b * SS;
        for (int s = tid; s < SS; s += 256) cnt += (p[s] != 0);
    }
    #pragma unroll
    for (int o = 16; o; o >>= 1) cnt += __shfl_xor_sync(0xffffffffu, cnt, o);
    if (lane == 0) slen[w] = cnt;
    __syncthreads();
    if (tid == 0) {
        int L = 0;
        #pragma unroll
        for (int i = 0; i < 8; i++) L += slen[i];
        g_len[b] = L;
        len_sh = L;
    }
    __syncthreads();
    const int len = len_sh;

    const int* tg = tags + (size_t)b * SS;
    const float* fb = feats + (size_t)b * SS * TT;
    int s0 = w << 7;
    int s1 = min(len, s0 + 128);
    double acc = 0.0;
    for (int s = s0 + lane; s < s1; s += 32) {
        int tag  = tg[s];
        int prev = (s == 0) ? START_TAG : tg[s - 1];
        acc += (double)fb[(size_t)s * TT + tag] + (double)tr[prev * TT + tag];
    }
    #pragma unroll
    for (int o = 16; o; o >>= 1) acc += __shfl_xor_sync(0xffffffffu, acc, o);
    if (lane == 0) {
        if (((len - 1) >> 7) == w)
            acc += (double)tr[tg[len - 1] * TT + END_TAG];
        sgold[w] = acc;
    }
    __syncthreads();
    if (tid == 0) {
        double g = 0.0;
        #pragma unroll
        for (int i = 0; i < 8; i++) g += sgold[i];
        g_gold[b] = g;
    }
}

// ---------------- forward/backward scan, single-warp CTAs ----------------
// CTA 0..511: forward alpha over s=0..m; CTA 512..1023: backward beta over
// s=len-1..m, m=(len-1)/2. One warp per CTA: thread t<26 owns the adjacent
// tag pair (2t, 2t+1); both matvecs share the 13 LDS.128 q-loads. No
// __syncthreads anywhere in the step loop — within-warp lockstep plus one
// __syncwarp() (compiler/memory fence) replaces the 2-warp barrier.
__global__ void __launch_bounds__(32, 1) k_main(const float* __restrict__ feats,
                                                const float* __restrict__ tr) {
    const int cta = blockIdx.x;
    const int b = cta & (BB - 1);
    const bool isFwd = cta < BB;
    const int t = threadIdx.x;            // 0..31
    const bool act = (t < 26);
    const int tcl = act ? t : 25;         // clamped for safe addressing
    const int jA = act ? 2 * t : 50;
    const int jB = act ? 2 * t + 1 : 51;
    __shared__ __align__(16) float shq[2][64];

    const int len = g_len[b];
    const int m = (len - 1) >> 1;
    const float* fb = feats + (size_t)b * SS * TT;
    const ull L2E2 = f2pack(LOG2E, LOG2E);

    if (isFwd) {
        const int L = m + 1;              // steps s=1..m
        // E columns jA, jB packed over i-pairs
        ull EpA[26], EpB[26];
        #pragma unroll
        for (int c = 0; c < 26; c++) {
            EpA[c] = f2pack(g_E[(2 * c) * TT + jA], g_E[(2 * c + 1) * TT + jA]);
            EpB[c] = f2pack(g_E[(2 * c) * TT + jB], g_E[(2 * c + 1) * TT + jB]);
        }

        // init: part0 = feats[b,0,:] + trans[START,:]
        float p0A = act ? (fb[jA] + tr[START_TAG * TT + jA]) : -1e30f;
        float p0B = act ? (fb[jB] + tr[START_TAG * TT + jB]) : -1e30f;
        float mx = fmaxf(p0A, p0B);
        #pragma unroll
        for (int o = 16; o; o >>= 1)
            mx = fmaxf(mx, __shfl_xor_sync(0xffffffffu, mx, o));
        const float m0 = mx;
        float uA = act ? ex2((p0A - m0) * LOG2E) : 0.0f;
        float uB = act ? ex2((p0B - m0) * LOG2E) : 0.0f;
        ((float2*)shq[0])[t] = make_float2(uA, uB);
        int Ktot = 0;
        __syncwarp();

        // emission pair prefetch (distance 4), pre-scaled by log2e
        const float2* pe = (const float2*)fb + tcl;   // stride 26 float2/step
        ull fl0 = 0, fl1 = 0, fl2 = 0, fl3 = 0;
        if (1 < L) { float2 v = pe[1 * 26]; fl0 = f2mul(f2pack(v.x, v.y), L2E2); }
        if (2 < L) { float2 v = pe[2 * 26]; fl1 = f2mul(f2pack(v.x, v.y), L2E2); }
        if (3 < L) { float2 v = pe[3 * 26]; fl2 = f2mul(f2pack(v.x, v.y), L2E2); }
        if (4 < L) { float2 v = pe[4 * 26]; fl3 = f2mul(f2pack(v.x, v.y), L2E2); }

        for (int s = 1; s < L; s++) {
            float2 fc = f2unpack(fl0);
            float efA = ex2(fc.x), efB = ex2(fc.y);
            fl0 = fl1; fl1 = fl2; fl2 = fl3;
            int sp = s + 4;
            float2 nv = make_float2(0.f, 0.f);
            if (sp < L) nv = pe[sp * 26];
            fl3 = f2mul(f2pack(nv.x, nv.y), L2E2);

            const ulonglong2* q8 = (const ulonglong2*)shq[(s - 1) & 1];
            ulonglong2 qv[13];
            #pragma unroll
            for (int c = 0; c < 13; c++) qv[c] = q8[c];

            float q0 = f2lo(qv[0].x);
            int ex = ((__float_as_int(q0) >> 23) & 0xFF) - 127;
            Ktot += ex;
            float scale = __int_as_float((127 - ex) << 23);
            float preA = scale * efA, preB = scale * efB;

            uA = matvec26(qv, EpA) * preA;
            uB = matvec26(qv, EpB) * preB;

            float2 st = act ? make_float2(uA, uB) : make_float2(0.f, 0.f);
            ((float2*)shq[s & 1])[t] = st;
            __syncwarp();
        }
        if (act) ((float2*)g_alpha[b])[t] = make_float2(uA, uB);
        if (t == 0) { g_Ka[b] = Ktot; g_m0[b] = m0; }
    } else {
        const int N = len - 1 - m;        // iterations: s = len-2 .. m
        // E rows jA, jB packed over column-pairs (contiguous 8B loads)
        ull EpA[26], EpB[26];
        const ull* ErA = (const ull*)(g_E + jA * TT);
        const ull* ErB = (const ull*)(g_E + jB * TT);
        #pragma unroll
        for (int c = 0; c < 26; c++) { EpA[c] = ErA[c]; EpB[c] = ErB[c]; }

        float EendA = g_E[jA * TT + END_TAG];
        float EendB = g_E[jB * TT + END_TAG];
        float uA, uB;
        if (len >= 2) {
            const float* fl = fb + (size_t)(len - 1) * TT;
            uA = ex2(fl[jA] * LOG2E) * EendA;
            uB = ex2(fl[jB] * LOG2E) * EendB;
        } else {
            uA = EendA; uB = EendB;       // len==1: beta = E[:,END], no ef
        }
        if (!act) { uA = 0.f; uB = 0.f; }
        ((float2*)shq[0])[t] = make_float2(uA, uB);
        int Ktot = 0;
        __syncwarp();

        // emission f_s needed only for iterations k <= N-2 (ef==1 at s==m)
        const float2* pb = (const float2*)fb + tcl;
        ull fl0 = 0, fl1 = 0, fl2 = 0, fl3 = 0;
        if (N >= 2) { float2 v = pb[(size_t)(len - 2) * 26]; fl0 = f2mul(f2pack(v.x, v.y), L2E2); }
        if (N >= 3) { float2 v = pb[(size_t)(len - 3) * 26]; fl1 = f2mul(f2pack(v.x, v.y), L2E2); }
        if (N >= 4) { float2 v = pb[(size_t)(len - 4) * 26]; fl2 = f2mul(f2pack(v.x, v.y), L2E2); }
        if (N >= 5) { float2 v = pb[(size_t)(len - 5) * 26]; fl3 = f2mul(f2pack(v.x, v.y), L2E2); }

        for (int k = 0; k < N; k++) {
            float2 fc = f2unpack(fl0);
            float efA = ex2(fc.x), efB = ex2(fc.y);
            fl0 = fl1; fl1 = fl2; fl2 = fl3;
            int kk = k + 4;
            float2 nv = make_float2(0.f, 0.f);
            if (kk <= N - 2) nv = pb[(size_t)(len - 2 - kk) * 26];
            fl3 = f2mul(f2pack(nv.x, nv.y), L2E2);

            const ulonglong2* q8 = (const ulonglong2*)shq[k & 1];
            ulonglong2 qv[13];
            #pragma unroll
            for (int c = 0; c < 13; c++) qv[c] = q8[c];

            float q0 = f2lo(qv[0].x);
            int ex = ((__float_as_int(q0) >> 23) & 0xFF) - 127;
            Ktot += ex;
            float scale = __int_as_float((127 - ex) << 23);
            float preA = scale * efA, preB = scale * efB;

            uA = matvec26(qv, EpA) * preA;
            uB = matvec26(qv, EpB) * preB;

            float2 st = act ? make_float2(uA, uB) : make_float2(0.f, 0.f);
            ((float2*)shq[(k + 1) & 1])[t] = st;
            __syncwarp();
        }
        if (act) ((float2*)g_beta[b])[t] = make_float2(uA, uB);
        if (t == 0) g_Kb[b] = Ktot;
    }
}

// ---------------- combine + reduce in one kernel ----------------
__global__ void k_final(float* out) {
    __shared__ double sh[16];
    int b = threadIdx.x;   // 512 threads, one per sequence
    double d = 0.0;
    #pragma unroll 4
    for (int i = 0; i < TT; i++)
        d += (double)g_alpha[b][i] * (double)g_beta[b][i];
    double a = (double)g_m0[b] + (double)(g_Ka[b] + g_Kb[b]) * LN2 + log(d)
               - g_gold[b];
    #pragma unroll
    for (int o = 16; o; o >>= 1) a += __shfl_xor_sync(0xffffffffu, a, o);
    if ((b & 31) == 0) sh[b >> 5] = a;
    __syncthreads();
    if (b < 32) {
        double v = (b < 16) ? sh[b] : 0.0;
        #pragma unroll
        for (int o = 8; o; o >>= 1) v += __shfl_xor_sync(0xffffffffu, v, o);
        if (b == 0) out[0] = (float)v;
    }
}

// ---------------- launch ----------------
extern "C" void kernel_launch(void* const* d_in, const int* in_sizes, int n_in,
                              void* d_out, int out_size) {
    const float* feats = (const float*)d_in[0];
    const void*  mask  = d_in[1];
    const int*   tags  = (const int*)d_in[2];
    const float* tr    = (const float*)d_in[3];
    float* out = (float*)d_out;

    k_detect<<<1, 256>>>(mask, tr);
    k_lengold<<<BB, 256>>>(mask, feats, tags, tr);
    k_main<<<2 * BB, 32>>>(feats, tr);
    k_final<<<1, 512>>>(out);
}